// round 2
// baseline (speedup 1.0000x reference)
#include <cuda_runtime.h>

#define NB    16
#define SLEN  2048
#define NTOK  (NB * SLEN)
#define HDIM  256
#define FDIM  512
#define CHUNK 512
#define LOG2E 1.4426950408889634f

struct LayerConsts {
    float A2[16];   // log2e * bw^2 * (Wq Wk^T)
    float M2[16];   // 0.5 * log2e * bw^2 * (Wk Wk^T)
    float Cm[16];   // Wv Wo
    float cvec[4];  // log2e * bw^2 * (Wk bq - Wk bk)
    float d0[4];    // Wo^T bv + bo
    float cconst;   // log2e * bw^2 * (bq.bk - 0.5 |bk|^2)
};

__device__ LayerConsts d_consts[2];
__device__ float4 d_X[NTOK];
__device__ float4 d_g[NTOK];    // log2-domain logit vector per key
__device__ float4 d_vf[NTOK];   // value vector per key
__device__ float  d_c[NTOK];    // log2-domain logit constant per key

// ---------------------------------------------------------------------------
// Per-layer 4x4 constant matrices (contractions over H=256)
// ---------------------------------------------------------------------------
__global__ void k_consts(const float* __restrict__ Wq, const float* __restrict__ bq,
                         const float* __restrict__ Wk, const float* __restrict__ bk,
                         const float* __restrict__ Wv, const float* __restrict__ bv,
                         const float* __restrict__ Wo, const float* __restrict__ bo,
                         const float* __restrict__ bw)
{
    int l = blockIdx.x;
    int tid = threadIdx.x;
    const float* wq  = Wq + l * 4 * HDIM;
    const float* wk  = Wk + l * 4 * HDIM;
    const float* wv  = Wv + l * 4 * HDIM;
    const float* wo  = Wo + l * HDIM * 4;
    const float* bql = bq + l * HDIM;
    const float* bkl = bk + l * HDIM;
    const float* bvl = bv + l * HDIM;

    __shared__ float sA[16], sM[16], sC[16], skq[4], sw[4], sd0[4], s0, sb2;

    if (tid < 16) {
        int i = tid >> 2, j = tid & 3;
        float a = 0.f, mm = 0.f, cc = 0.f;
        for (int h = 0; h < HDIM; ++h) {
            a  = fmaf(wq[i * HDIM + h], wk[j * HDIM + h], a);
            mm = fmaf(wk[i * HDIM + h], wk[j * HDIM + h], mm);
            cc = fmaf(wv[i * HDIM + h], wo[h * 4 + j], cc);
        }
        sA[tid] = a; sM[tid] = mm; sC[tid] = cc;
    } else if (tid < 20) {
        int i = tid - 16;
        float q = 0.f, w = 0.f;
        for (int h = 0; h < HDIM; ++h) {
            q = fmaf(wk[i * HDIM + h], bql[h], q);
            w = fmaf(wk[i * HDIM + h], bkl[h], w);
        }
        skq[i] = q; sw[i] = w;
    } else if (tid < 24) {
        int j = tid - 20;
        float d = 0.f;
        for (int h = 0; h < HDIM; ++h) d = fmaf(bvl[h], wo[h * 4 + j], d);
        sd0[j] = d + bo[l * 4 + j];
    } else if (tid == 24) {
        float s = 0.f;
        for (int h = 0; h < HDIM; ++h) s = fmaf(bql[h], bkl[h], s);
        s0 = s;
    } else if (tid == 25) {
        float s = 0.f;
        for (int h = 0; h < HDIM; ++h) s = fmaf(bkl[h], bkl[h], s);
        sb2 = s;
    }
    __syncthreads();

    float b2w = bw[l] * bw[l];
    float sc = LOG2E * b2w;
    LayerConsts* C = &d_consts[l];
    if (tid < 16) {
        C->A2[tid] = sc * sA[tid];
        C->M2[tid] = 0.5f * sc * sM[tid];
        C->Cm[tid] = sC[tid];
    }
    if (tid < 4) {
        C->cvec[tid] = sc * (skq[tid] - sw[tid]);
        C->d0[tid]   = sd0[tid];
    }
    if (tid == 0) C->cconst = sc * (s0 - 0.5f * sb2);
}

// ---------------------------------------------------------------------------
// Per-token key features (function of this token's x only)
// ---------------------------------------------------------------------------
__device__ __forceinline__ void compute_feat(int l, float4 xv, int t)
{
    const LayerConsts& C = d_consts[l];
    float x[4] = {xv.x, xv.y, xv.z, xv.w};
    float g[4], v[4];
    float c = C.cconst;
    #pragma unroll
    for (int i = 0; i < 4; ++i) {
        float gi = 0.f, mi = 0.f, vi = 0.f;
        #pragma unroll
        for (int j = 0; j < 4; ++j) {
            gi = fmaf(C.A2[i * 4 + j], x[j], gi);
            mi = fmaf(C.M2[i * 4 + j], x[j], mi);
            vi = fmaf(C.Cm[j * 4 + i], x[j], vi);
        }
        g[i] = gi; v[i] = vi;
        c = fmaf(C.cvec[i] - mi, x[i], c);
    }
    d_g[t]  = make_float4(g[0], g[1], g[2], g[3]);
    d_vf[t] = make_float4(v[0], v[1], v[2], v[3]);
    d_c[t]  = c;
}

__global__ void k_init(const float* __restrict__ KEY, const float* __restrict__ VAL)
{
    int t = blockIdx.x * blockDim.x + threadIdx.x;
    if (t >= NTOK) return;
    float4 x = make_float4(KEY[3 * t + 0], KEY[3 * t + 1], KEY[3 * t + 2], VAL[t]);
    d_X[t] = x;
    compute_feat(0, x, t);
}

__device__ __forceinline__ void ln4(float h[4], const float* __restrict__ g,
                                    const float* __restrict__ be, int l)
{
    float mean = 0.25f * (h[0] + h[1] + h[2] + h[3]);
    float e0 = h[0] - mean, e1 = h[1] - mean, e2 = h[2] - mean, e3 = h[3] - mean;
    float var = 0.25f * (e0 * e0 + e1 * e1 + e2 * e2 + e3 * e3);
    float r = rsqrtf(var + 1e-5f);
    h[0] = fmaf(e0 * r, g[l * 4 + 0], be[l * 4 + 0]);
    h[1] = fmaf(e1 * r, g[l * 4 + 1], be[l * 4 + 1]);
    h[2] = fmaf(e2 * r, g[l * 4 + 2], be[l * 4 + 2]);
    h[3] = fmaf(e3 * r, g[l * 4 + 3], be[l * 4 + 3]);
}

__device__ __forceinline__ float fast_exp2(float x)
{
    float r;
    asm("ex2.approx.ftz.f32 %0, %1;" : "=f"(r) : "f"(x));
    return r;
}

// ---------------------------------------------------------------------------
// Fused attention + LN1 + FFN + LN2 (+ next-layer features or final fc).
// grid (32 tiles, 16 batches), 64 threads, 1 query per thread.
// Logits are <= max + ~10 in exp2 domain by construction (true logit <= 0,
// per-query softmax-invariant shift cancels exactly in the normalization).
// ---------------------------------------------------------------------------
template <int LAYER>
__global__ void __launch_bounds__(64, 4)
k_att(float* __restrict__ out,
      const float* __restrict__ W1, const float* __restrict__ b1,
      const float* __restrict__ W2, const float* __restrict__ b2,
      const float* __restrict__ g1, const float* __restrict__ be1,
      const float* __restrict__ g2, const float* __restrict__ be2,
      const float* __restrict__ Wfc, const float* __restrict__ bfc)
{
    __shared__ float4 sG[CHUNK];
    __shared__ float4 sV[CHUNK];
    __shared__ float  sC[CHUNK];
    __shared__ float4 sW1[FDIM];   // columns of W1 (4 input dims)
    __shared__ float  sB1[FDIM];
    __shared__ float4 sW2[FDIM];   // rows of W2

    int b = blockIdx.y, tid = threadIdx.x;
    int base = b * SLEN;
    int q = base + blockIdx.x * 64 + tid;

    const float* w1 = W1 + LAYER * 4 * FDIM;
    const float* w2 = W2 + LAYER * FDIM * 4;
    for (int f = tid; f < FDIM; f += 64) {
        sW1[f] = make_float4(w1[f], w1[FDIM + f], w1[2 * FDIM + f], w1[3 * FDIM + f]);
        sB1[f] = b1[LAYER * FDIM + f];
        sW2[f] = *(const float4*)(w2 + f * 4);
    }

    float4 xq = d_X[q];

    float  ss0 = 0.f, ss1 = 0.f, ss2 = 0.f, ss3 = 0.f;
    float4 ac0 = make_float4(0.f, 0.f, 0.f, 0.f);
    float4 ac1 = make_float4(0.f, 0.f, 0.f, 0.f);
    float4 ac2 = make_float4(0.f, 0.f, 0.f, 0.f);
    float4 ac3 = make_float4(0.f, 0.f, 0.f, 0.f);

    for (int co = 0; co < SLEN; co += CHUNK) {
        __syncthreads();
        for (int k = tid; k < CHUNK; k += 64) {
            sG[k] = d_g[base + co + k];
            sV[k] = d_vf[base + co + k];
            sC[k] = d_c[base + co + k];
        }
        __syncthreads();

        #pragma unroll 2
        for (int k = 0; k < CHUNK; k += 4) {
            {
                float4 g = sG[k]; float c = sC[k];
                float l = fmaf(xq.x, g.x, fmaf(xq.y, g.y, fmaf(xq.z, g.z, fmaf(xq.w, g.w, c))));
                float p = fast_exp2(l);
                float4 v = sV[k];
                ss0 += p;
                ac0.x = fmaf(p, v.x, ac0.x); ac0.y = fmaf(p, v.y, ac0.y);
                ac0.z = fmaf(p, v.z, ac0.z); ac0.w = fmaf(p, v.w, ac0.w);
            }
            {
                float4 g = sG[k + 1]; float c = sC[k + 1];
                float l = fmaf(xq.x, g.x, fmaf(xq.y, g.y, fmaf(xq.z, g.z, fmaf(xq.w, g.w, c))));
                float p = fast_exp2(l);
                float4 v = sV[k + 1];
                ss1 += p;
                ac1.x = fmaf(p, v.x, ac1.x); ac1.y = fmaf(p, v.y, ac1.y);
                ac1.z = fmaf(p, v.z, ac1.z); ac1.w = fmaf(p, v.w, ac1.w);
            }
            {
                float4 g = sG[k + 2]; float c = sC[k + 2];
                float l = fmaf(xq.x, g.x, fmaf(xq.y, g.y, fmaf(xq.z, g.z, fmaf(xq.w, g.w, c))));
                float p = fast_exp2(l);
                float4 v = sV[k + 2];
                ss2 += p;
                ac2.x = fmaf(p, v.x, ac2.x); ac2.y = fmaf(p, v.y, ac2.y);
                ac2.z = fmaf(p, v.z, ac2.z); ac2.w = fmaf(p, v.w, ac2.w);
            }
            {
                float4 g = sG[k + 3]; float c = sC[k + 3];
                float l = fmaf(xq.x, g.x, fmaf(xq.y, g.y, fmaf(xq.z, g.z, fmaf(xq.w, g.w, c))));
                float p = fast_exp2(l);
                float4 v = sV[k + 3];
                ss3 += p;
                ac3.x = fmaf(p, v.x, ac3.x); ac3.y = fmaf(p, v.y, ac3.y);
                ac3.z = fmaf(p, v.z, ac3.z); ac3.w = fmaf(p, v.w, ac3.w);
            }
        }
    }

    float ssum = (ss0 + ss1) + (ss2 + ss3);
    float a0 = (ac0.x + ac1.x) + (ac2.x + ac3.x);
    float a1 = (ac0.y + ac1.y) + (ac2.y + ac3.y);
    float a2 = (ac0.z + ac1.z) + (ac2.z + ac3.z);
    float a3 = (ac0.w + ac1.w) + (ac2.w + ac3.w);

    const LayerConsts& Cs = d_consts[LAYER];
    float inv = 1.0f / ssum;
    float h[4];
    h[0] = xq.x + fmaf(a0, inv, Cs.d0[0]);
    h[1] = xq.y + fmaf(a1, inv, Cs.d0[1]);
    h[2] = xq.z + fmaf(a2, inv, Cs.d0[2]);
    h[3] = xq.w + fmaf(a3, inv, Cs.d0[3]);

    ln4(h, g1, be1, LAYER);
    float r0 = h[0], r1 = h[1], r2 = h[2], r3 = h[3];

    // FFN, two accumulator banks for ILP
    float o0a = b2[LAYER * 4 + 0], o1a = b2[LAYER * 4 + 1];
    float o2a = b2[LAYER * 4 + 2], o3a = b2[LAYER * 4 + 3];
    float o0b = 0.f, o1b = 0.f, o2b = 0.f, o3b = 0.f;
    #pragma unroll 2
    for (int f = 0; f < FDIM; f += 2) {
        float4 c1 = sW1[f];
        float hf = fmaf(r0, c1.x, fmaf(r1, c1.y, fmaf(r2, c1.z, fmaf(r3, c1.w, sB1[f]))));
        hf = fmaxf(hf, 0.f);
        float4 c2 = sW2[f];
        o0a = fmaf(hf, c2.x, o0a); o1a = fmaf(hf, c2.y, o1a);
        o2a = fmaf(hf, c2.z, o2a); o3a = fmaf(hf, c2.w, o3a);

        float4 d1 = sW1[f + 1];
        float hg = fmaf(r0, d1.x, fmaf(r1, d1.y, fmaf(r2, d1.z, fmaf(r3, d1.w, sB1[f + 1]))));
        hg = fmaxf(hg, 0.f);
        float4 d2 = sW2[f + 1];
        o0b = fmaf(hg, d2.x, o0b); o1b = fmaf(hg, d2.y, o1b);
        o2b = fmaf(hg, d2.z, o2b); o3b = fmaf(hg, d2.w, o3b);
    }

    float h2[4] = {r0 + o0a + o0b, r1 + o1a + o1b, r2 + o2a + o2b, r3 + o3a + o3b};
    ln4(h2, g2, be2, LAYER);
    float4 nx = make_float4(h2[0], h2[1], h2[2], h2[3]);

    if (LAYER == 0) {
        d_X[q] = nx;
        compute_feat(1, nx, q);
    } else {
        out[q] = fmaf(nx.x, Wfc[0], fmaf(nx.y, Wfc[1],
                 fmaf(nx.z, Wfc[2], fmaf(nx.w, Wfc[3], bfc[0]))));
    }
}

extern "C" void kernel_launch(void* const* d_in, const int* in_sizes, int n_in,
                              void* d_out, int out_size)
{
    const float* KEY   = (const float*)d_in[0];
    const float* VALUE = (const float*)d_in[1];
    const float* Wq    = (const float*)d_in[2];
    const float* bq    = (const float*)d_in[3];
    const float* Wk    = (const float*)d_in[4];
    const float* bk    = (const float*)d_in[5];
    const float* Wv    = (const float*)d_in[6];
    const float* bv    = (const float*)d_in[7];
    const float* Wo    = (const float*)d_in[8];
    const float* bo    = (const float*)d_in[9];
    const float* bw    = (const float*)d_in[10];
    const float* g1    = (const float*)d_in[11];
    const float* be1   = (const float*)d_in[12];
    const float* W1    = (const float*)d_in[13];
    const float* b1    = (const float*)d_in[14];
    const float* W2    = (const float*)d_in[15];
    const float* b2    = (const float*)d_in[16];
    const float* g2    = (const float*)d_in[17];
    const float* be2   = (const float*)d_in[18];
    const float* Wfc   = (const float*)d_in[19];
    const float* bfc   = (const float*)d_in[20];

    k_consts<<<2, 32>>>(Wq, bq, Wk, bk, Wv, bv, Wo, bo, bw);
    k_init<<<NTOK / 256, 256>>>(KEY, VALUE);
    k_att<0><<<dim3(32, 16), 64>>>(nullptr, W1, b1, W2, b2, g1, be1, g2, be2, Wfc, bfc);
    k_att<1><<<dim3(32, 16), 64>>>((float*)d_out, W1, b1, W2, b2, g1, be1, g2, be2, Wfc, bfc);
}

// round 5
// speedup vs baseline: 1.6312x; 1.6312x over previous
#include <cuda_runtime.h>

typedef unsigned long long ull;

#define NB    16
#define SLEN  2048
#define NTOK  (NB * SLEN)
#define HDIM  256
#define FDIM  512
#define NREC  (SLEN / 2)   // key-pair records
#define FREC  (FDIM / 2)   // ffn-pair records
#define LOG2E 1.4426950408889634f

struct LayerConsts {
    float A2[16];   // log2e*bw^2 * Wq Wk^T
    float M2[16];   // 0.5*log2e*bw^2 * Wk Wk^T
    float Cm[16];   // Wv Wo
    float cvec[4];  // log2e*bw^2 * (Wk bq - Wk bk)
    float d0[4];    // Wo^T bv + bo
    float cconst;   // log2e*bw^2 * (bq.bk - 0.5|bk|^2)
};

__device__ LayerConsts d_consts[2];
__device__ float4 d_X[NTOK];
__device__ float  d_c[NTOK];
// pre-interleaved FFN weights (pairs over f)
__device__ ulonglong2 d_f1[2][FREC];
__device__ ulonglong2 d_f2[2][FREC];
__device__ ulonglong2 d_f3[2][FREC];
__device__ ulonglong2 d_f4[2][FREC];
__device__ ull        d_fb[2][FREC];

// ---------------- packed fp32x2 helpers ----------------
__device__ __forceinline__ ull fma2(ull a, ull b, ull c) {
    ull d; asm("fma.rn.f32x2 %0, %1, %2, %3;" : "=l"(d) : "l"(a), "l"(b), "l"(c)); return d;
}
__device__ __forceinline__ ull add2(ull a, ull b) {
    ull d; asm("add.rn.f32x2 %0, %1, %2;" : "=l"(d) : "l"(a), "l"(b)); return d;
}
__device__ __forceinline__ ull pk2(float lo, float hi) {
    ull r; asm("mov.b64 %0, {%1, %2};" : "=l"(r) : "f"(lo), "f"(hi)); return r;
}
__device__ __forceinline__ float2 upk2(ull x) {
    float2 r; asm("mov.b64 {%0, %1}, %2;" : "=f"(r.x), "=f"(r.y) : "l"(x)); return r;
}
__device__ __forceinline__ float fast_exp2(float x) {
    float r; asm("ex2.approx.ftz.f32 %0, %1;" : "=f"(r) : "f"(x)); return r;
}

// ---------------------------------------------------------------------------
// Per-layer constants + FFN weight interleave. 2 blocks x 256 threads.
// ---------------------------------------------------------------------------
__global__ void k_consts(const float* __restrict__ Wq, const float* __restrict__ bq,
                         const float* __restrict__ Wk, const float* __restrict__ bk,
                         const float* __restrict__ Wv, const float* __restrict__ bv,
                         const float* __restrict__ Wo, const float* __restrict__ bo,
                         const float* __restrict__ bw,
                         const float* __restrict__ W1, const float* __restrict__ b1,
                         const float* __restrict__ W2)
{
    int l = blockIdx.x;
    int h = threadIdx.x;   // 0..255
    __shared__ float acc[64];
    if (h < 64) acc[h] = 0.f;
    __syncthreads();

    // --- pack FFN weights: one f-pair per thread ---
    {
        int f = 2 * h;
        const float* w1 = W1 + l * 4 * FDIM;
        const float* w2 = W2 + l * FDIM * 4;
        d_f1[l][h] = make_ulonglong2(pk2(w1[0 * FDIM + f], w1[0 * FDIM + f + 1]),
                                     pk2(w1[1 * FDIM + f], w1[1 * FDIM + f + 1]));
        d_f2[l][h] = make_ulonglong2(pk2(w1[2 * FDIM + f], w1[2 * FDIM + f + 1]),
                                     pk2(w1[3 * FDIM + f], w1[3 * FDIM + f + 1]));
        d_fb[l][h] = pk2(b1[l * FDIM + f], b1[l * FDIM + f + 1]);
        float4 r0 = *(const float4*)(w2 + f * 4);
        float4 r1 = *(const float4*)(w2 + (f + 1) * 4);
        d_f3[l][h] = make_ulonglong2(pk2(r0.x, r1.x), pk2(r0.y, r1.y));
        d_f4[l][h] = make_ulonglong2(pk2(r0.z, r1.z), pk2(r0.w, r1.w));
    }

    // --- 4x4 contractions over H: one h per thread, shfl + atomic reduce ---
    const float* wq = Wq + l * 4 * HDIM;
    const float* wk = Wk + l * 4 * HDIM;
    const float* wv = Wv + l * 4 * HDIM;
    const float* wo = Wo + l * HDIM * 4;
    float qv[4], kv[4], vv[4], ov[4];
    #pragma unroll
    for (int i = 0; i < 4; ++i) {
        qv[i] = wq[i * HDIM + h];
        kv[i] = wk[i * HDIM + h];
        vv[i] = wv[i * HDIM + h];
        ov[i] = wo[h * 4 + i];
    }
    float bqv = bq[l * HDIM + h], bkv = bk[l * HDIM + h], bvv = bv[l * HDIM + h];

    float vals[62];
    int n = 0;
    #pragma unroll
    for (int i = 0; i < 4; ++i)
        #pragma unroll
        for (int j = 0; j < 4; ++j) vals[n++] = qv[i] * kv[j];   // A 0..15
    #pragma unroll
    for (int i = 0; i < 4; ++i)
        #pragma unroll
        for (int j = 0; j < 4; ++j) vals[n++] = kv[i] * kv[j];   // M 16..31
    #pragma unroll
    for (int i = 0; i < 4; ++i)
        #pragma unroll
        for (int j = 0; j < 4; ++j) vals[n++] = vv[i] * ov[j];   // Cm 32..47
    #pragma unroll
    for (int i = 0; i < 4; ++i) vals[n++] = kv[i] * bqv;         // 48..51
    #pragma unroll
    for (int i = 0; i < 4; ++i) vals[n++] = kv[i] * bkv;         // 52..55
    #pragma unroll
    for (int j = 0; j < 4; ++j) vals[n++] = bvv * ov[j];         // 56..59
    vals[60] = bqv * bkv;
    vals[61] = bkv * bkv;

    #pragma unroll
    for (int v = 0; v < 62; ++v) {
        float x = vals[v];
        x += __shfl_xor_sync(0xffffffffu, x, 16);
        x += __shfl_xor_sync(0xffffffffu, x, 8);
        x += __shfl_xor_sync(0xffffffffu, x, 4);
        x += __shfl_xor_sync(0xffffffffu, x, 2);
        x += __shfl_xor_sync(0xffffffffu, x, 1);
        if ((h & 31) == 0) atomicAdd(&acc[v], x);
    }
    __syncthreads();

    float sc = LOG2E * bw[l] * bw[l];
    LayerConsts* C = &d_consts[l];
    if (h < 16) {
        C->A2[h] = sc * acc[h];
        C->M2[h] = 0.5f * sc * acc[16 + h];
        C->Cm[h] = acc[32 + h];
    } else if (h < 20) {
        int i = h - 16;
        C->cvec[i] = sc * (acc[48 + i] - acc[52 + i]);
        C->d0[i]   = acc[56 + i] + bo[l * 4 + i];
    } else if (h == 20) {
        C->cconst = sc * (acc[60] - 0.5f * acc[61]);
    }
}

// per-key logit constant c = cconst + sum_i (cvec_i - (M2 x)_i) x_i
__device__ __forceinline__ float cfeat(const LayerConsts& C, float4 xv)
{
    float x[4] = {xv.x, xv.y, xv.z, xv.w};
    float c = C.cconst;
    #pragma unroll
    for (int i = 0; i < 4; ++i) {
        float mi = 0.f;
        #pragma unroll
        for (int j = 0; j < 4; ++j) mi = fmaf(C.M2[i * 4 + j], x[j], mi);
        c = fmaf(C.cvec[i] - mi, x[i], c);
    }
    return c;
}

__device__ __forceinline__ void ln4(float h[4], const float* __restrict__ g,
                                    const float* __restrict__ be, int l)
{
    float mean = 0.25f * (h[0] + h[1] + h[2] + h[3]);
    float e0 = h[0] - mean, e1 = h[1] - mean, e2 = h[2] - mean, e3 = h[3] - mean;
    float var = 0.25f * (e0 * e0 + e1 * e1 + e2 * e2 + e3 * e3);
    float r = rsqrtf(var + 1e-5f);
    h[0] = fmaf(e0 * r, g[l * 4 + 0], be[l * 4 + 0]);
    h[1] = fmaf(e1 * r, g[l * 4 + 1], be[l * 4 + 1]);
    h[2] = fmaf(e2 * r, g[l * 4 + 2], be[l * 4 + 2]);
    h[3] = fmaf(e3 * r, g[l * 4 + 3], be[l * 4 + 3]);
}

// ---------------------------------------------------------------------------
// Fused attention + LN1 + FFN + LN2 (+ next-layer feat / final fc).
// grid (32, 16), 64 threads, 1 query per thread, f32x2-packed over key pairs.
// True logit <= 0 with max exactly 0 on the diagonal; the per-query
// softmax-invariant shift cancels in normalization -> no max pass, no overflow.
// Shared layout (40960 B total):
//   [0      , 16384) sKA : per-pair (x0.x,x1.x),(x0.y,x1.y)
//   [16384  , 32768) sKB : per-pair (x0.z,x1.z),(x0.w,x1.w)
//   [32768  , 40960) sKC : per-pair (c0,c1)
// FFN overlay reuses [0, 18432) after the attention loop.
// ---------------------------------------------------------------------------
#define SMEM_BYTES (NREC * 16 + NREC * 16 + NREC * 8)
static_assert(SMEM_BYTES == NREC * 40, "key smem layout mismatch");
static_assert(FREC * 16 * 4 + FREC * 8 <= SMEM_BYTES, "ffn overlay exceeds key smem");
static_assert(SMEM_BYTES <= 48 * 1024, "over static smem limit");

template <int LAYER>
__global__ void __launch_bounds__(64, 5)
k_att(const float* __restrict__ KEY, const float* __restrict__ VAL,
      float* __restrict__ out,
      const float* __restrict__ g1, const float* __restrict__ be1,
      const float* __restrict__ g2, const float* __restrict__ be2,
      const float* __restrict__ b2,
      const float* __restrict__ Wfc, const float* __restrict__ bfc)
{
    __shared__ __align__(16) unsigned char smraw[SMEM_BYTES];
    ulonglong2* sKA = (ulonglong2*)smraw;
    ulonglong2* sKB = (ulonglong2*)(smraw + NREC * 16);
    ull*        sKC = (ull*)(smraw + NREC * 32);
    // FFN overlay (written after attention phase): 18 KB
    ulonglong2* sF1 = (ulonglong2*)smraw;
    ulonglong2* sF2 = sF1 + FREC;
    ulonglong2* sF3 = sF2 + FREC;
    ulonglong2* sF4 = sF3 + FREC;
    ull*        sFB = (ull*)(sF4 + FREC);

    int tid = threadIdx.x;
    int base = blockIdx.y * SLEN;
    int q = base + blockIdx.x * 64 + tid;

    const LayerConsts& Cs = d_consts[LAYER];

    // ---- prefill key pairs ----
    for (int r = tid; r < NREC; r += 64) {
        int t0 = base + 2 * r;
        float4 x0, x1; float c0, c1;
        if (LAYER == 0) {
            x0 = make_float4(KEY[3 * t0], KEY[3 * t0 + 1], KEY[3 * t0 + 2], VAL[t0]);
            x1 = make_float4(KEY[3 * t0 + 3], KEY[3 * t0 + 4], KEY[3 * t0 + 5], VAL[t0 + 1]);
            c0 = cfeat(Cs, x0);
            c1 = cfeat(Cs, x1);
        } else {
            x0 = d_X[t0]; x1 = d_X[t0 + 1];
            c0 = d_c[t0]; c1 = d_c[t0 + 1];
        }
        sKA[r] = make_ulonglong2(pk2(x0.x, x1.x), pk2(x0.y, x1.y));
        sKB[r] = make_ulonglong2(pk2(x0.z, x1.z), pk2(x0.w, x1.w));
        sKC[r] = pk2(c0, c1);
    }

    float4 xq;
    if (LAYER == 0)
        xq = make_float4(KEY[3 * q], KEY[3 * q + 1], KEY[3 * q + 2], VAL[q]);
    else
        xq = d_X[q];

    // query-folded logit vector gq = A2^T xq, splatted into f32x2 pairs
    float gq0 = xq.x * Cs.A2[0] + xq.y * Cs.A2[4] + xq.z * Cs.A2[8]  + xq.w * Cs.A2[12];
    float gq1 = xq.x * Cs.A2[1] + xq.y * Cs.A2[5] + xq.z * Cs.A2[9]  + xq.w * Cs.A2[13];
    float gq2 = xq.x * Cs.A2[2] + xq.y * Cs.A2[6] + xq.z * Cs.A2[10] + xq.w * Cs.A2[14];
    float gq3 = xq.x * Cs.A2[3] + xq.y * Cs.A2[7] + xq.z * Cs.A2[11] + xq.w * Cs.A2[15];
    ull gx = pk2(gq0, gq0), gy = pk2(gq1, gq1), gz = pk2(gq2, gq2), gw = pk2(gq3, gq3);

    __syncthreads();

    // ---- attention main loop: 2 keys per iteration, packed ----
    ull sp = 0ull, a0 = 0ull, a1 = 0ull, a2 = 0ull, a3 = 0ull;
    #pragma unroll 4
    for (int r = 0; r < NREC; ++r) {
        ulonglong2 A = sKA[r];
        ulonglong2 B = sKB[r];
        ull lg = fma2(gx, A.x, sKC[r]);
        lg = fma2(gy, A.y, lg);
        lg = fma2(gz, B.x, lg);
        lg = fma2(gw, B.y, lg);
        float2 lf = upk2(lg);
        ull pp = pk2(fast_exp2(lf.x), fast_exp2(lf.y));
        sp = add2(sp, pp);
        a0 = fma2(pp, A.x, a0);
        a1 = fma2(pp, A.y, a1);
        a2 = fma2(pp, B.x, a2);
        a3 = fma2(pp, B.y, a3);
    }

    __syncthreads();   // key smem dead -> overlay with FFN weights

    for (int i = tid; i < FREC; i += 64) {
        sF1[i] = d_f1[LAYER][i];
        sF2[i] = d_f2[LAYER][i];
        sF3[i] = d_f3[LAYER][i];
        sF4[i] = d_f4[LAYER][i];
        sFB[i] = d_fb[LAYER][i];
    }

    // attention epilogue (register-only; overlaps the smem fill)
    float2 s2 = upk2(sp);
    float ssum = s2.x + s2.y;
    float2 u0 = upk2(a0), u1 = upk2(a1), u2 = upk2(a2), u3 = upk2(a3);
    float S0 = u0.x + u0.y, S1 = u1.x + u1.y, S2 = u2.x + u2.y, S3 = u3.x + u3.y;
    float inv = 1.0f / ssum;
    float h[4];
    #pragma unroll
    for (int j = 0; j < 4; ++j) {
        float vj = S0 * Cs.Cm[0 * 4 + j] + S1 * Cs.Cm[1 * 4 + j]
                 + S2 * Cs.Cm[2 * 4 + j] + S3 * Cs.Cm[3 * 4 + j];
        h[j] = ((&xq.x)[j]) + fmaf(vj, inv, Cs.d0[j]);
    }
    ln4(h, g1, be1, LAYER);
    float r0 = h[0], r1 = h[1], r2 = h[2], r3 = h[3];
    ull r0p = pk2(r0, r0), r1p = pk2(r1, r1), r2p = pk2(r2, r2), r3p = pk2(r3, r3);

    __syncthreads();

    // ---- FFN: 2 f-channels per iteration, packed ----
    ull o0 = 0ull, o1 = 0ull, o2 = 0ull, o3 = 0ull;
    #pragma unroll 4
    for (int t = 0; t < FREC; ++t) {
        ulonglong2 wa = sF1[t], wb = sF2[t];
        ull hp = fma2(r0p, wa.x, sFB[t]);
        hp = fma2(r1p, wa.y, hp);
        hp = fma2(r2p, wb.x, hp);
        hp = fma2(r3p, wb.y, hp);
        float2 hh = upk2(hp);
        ull hr = pk2(fmaxf(hh.x, 0.f), fmaxf(hh.y, 0.f));
        ulonglong2 va = sF3[t], vb = sF4[t];
        o0 = fma2(hr, va.x, o0);
        o1 = fma2(hr, va.y, o1);
        o2 = fma2(hr, vb.x, o2);
        o3 = fma2(hr, vb.y, o3);
    }
    float2 w0 = upk2(o0), w1v = upk2(o1), w2v = upk2(o2), w3v = upk2(o3);
    float h2[4];
    h2[0] = r0 + w0.x + w0.y + b2[LAYER * 4 + 0];
    h2[1] = r1 + w1v.x + w1v.y + b2[LAYER * 4 + 1];
    h2[2] = r2 + w2v.x + w2v.y + b2[LAYER * 4 + 2];
    h2[3] = r3 + w3v.x + w3v.y + b2[LAYER * 4 + 3];
    ln4(h2, g2, be2, LAYER);

    if (LAYER == 0) {
        float4 nx = make_float4(h2[0], h2[1], h2[2], h2[3]);
        d_X[q] = nx;
        d_c[q] = cfeat(d_consts[1], nx);
    } else {
        out[q] = fmaf(h2[0], Wfc[0], fmaf(h2[1], Wfc[1],
                 fmaf(h2[2], Wfc[2], fmaf(h2[3], Wfc[3], bfc[0]))));
    }
}

extern "C" void kernel_launch(void* const* d_in, const int* in_sizes, int n_in,
                              void* d_out, int out_size)
{
    const float* KEY   = (const float*)d_in[0];
    const float* VALUE = (const float*)d_in[1];
    const float* Wq    = (const float*)d_in[2];
    const float* bq    = (const float*)d_in[3];
    const float* Wk    = (const float*)d_in[4];
    const float* bk    = (const float*)d_in[5];
    const float* Wv    = (const float*)d_in[6];
    const float* bv    = (const float*)d_in[7];
    const float* Wo    = (const float*)d_in[8];
    const float* bo    = (const float*)d_in[9];
    const float* bw    = (const float*)d_in[10];
    const float* g1    = (const float*)d_in[11];
    const float* be1   = (const float*)d_in[12];
    const float* W1    = (const float*)d_in[13];
    const float* b1    = (const float*)d_in[14];
    const float* W2    = (const float*)d_in[15];
    const float* b2    = (const float*)d_in[16];
    const float* g2    = (const float*)d_in[17];
    const float* be2   = (const float*)d_in[18];
    const float* Wfc   = (const float*)d_in[19];
    const float* bfc   = (const float*)d_in[20];

    k_consts<<<2, 256>>>(Wq, bq, Wk, bk, Wv, bv, Wo, bo, bw, W1, b1, W2);
    k_att<0><<<dim3(32, 16), 64>>>(KEY, VALUE, nullptr, g1, be1, g2, be2, b2, Wfc, bfc);
    k_att<1><<<dim3(32, 16), 64>>>(KEY, VALUE, (float*)d_out, g1, be1, g2, be2, b2, Wfc, bfc);
}

// round 6
// speedup vs baseline: 1.8596x; 1.1400x over previous
#include <cuda_runtime.h>

typedef unsigned long long ull;

#define NB    16
#define SLEN  2048
#define NTOK  (NB * SLEN)
#define HDIM  256
#define FDIM  512
#define NREC  (SLEN / 2)   // key-pair records
#define FREC  (FDIM / 2)   // ffn-pair records
#define LOG2E 1.4426950408889634f

struct LayerConsts {
    float A2[16];   // log2e*bw^2 * Wq Wk^T
    float M2[16];   // 0.5*log2e*bw^2 * Wk Wk^T
    float Cm[16];   // Wv Wo
    float cvec[4];  // log2e*bw^2 * (Wk bq - Wk bk)
    float d0[4];    // Wo^T bv + bo
    float cconst;   // log2e*bw^2 * (bq.bk - 0.5|bk|^2)
};

__device__ LayerConsts d_consts[2];
__device__ float4 d_X[NTOK];
__device__ float  d_c[NTOK];
// pre-interleaved FFN weights (pairs over f)
__device__ ulonglong2 d_f1[2][FREC];
__device__ ulonglong2 d_f2[2][FREC];
__device__ ulonglong2 d_f3[2][FREC];
__device__ ulonglong2 d_f4[2][FREC];
__device__ ull        d_fb[2][FREC];

// ---------------- packed fp32x2 helpers ----------------
__device__ __forceinline__ ull fma2(ull a, ull b, ull c) {
    ull d; asm("fma.rn.f32x2 %0, %1, %2, %3;" : "=l"(d) : "l"(a), "l"(b), "l"(c)); return d;
}
__device__ __forceinline__ ull add2(ull a, ull b) {
    ull d; asm("add.rn.f32x2 %0, %1, %2;" : "=l"(d) : "l"(a), "l"(b)); return d;
}
__device__ __forceinline__ ull pk2(float lo, float hi) {
    ull r; asm("mov.b64 %0, {%1, %2};" : "=l"(r) : "f"(lo), "f"(hi)); return r;
}
__device__ __forceinline__ float2 upk2(ull x) {
    float2 r; asm("mov.b64 {%0, %1}, %2;" : "=f"(r.x), "=f"(r.y) : "l"(x)); return r;
}
__device__ __forceinline__ float fast_exp2(float x) {
    float r; asm("ex2.approx.ftz.f32 %0, %1;" : "=f"(r) : "f"(x)); return r;
}

// ---------------------------------------------------------------------------
// Per-layer constants. Warp-per-output: 62 dot products over H=256.
// Block 1024 (32 warps), grid 2 (one block per layer).
// ---------------------------------------------------------------------------
__device__ __forceinline__ float prod_for(int o, int h,
    const float* wq, const float* wk, const float* wv, const float* wo,
    const float* bql, const float* bkl, const float* bvl)
{
    if (o < 16)       return wq[(o >> 2) * HDIM + h] * wk[(o & 3) * HDIM + h];
    else if (o < 32)  { int u = o - 16; return wk[(u >> 2) * HDIM + h] * wk[(u & 3) * HDIM + h]; }
    else if (o < 48)  { int u = o - 32; return wv[(u >> 2) * HDIM + h] * wo[h * 4 + (u & 3)]; }
    else if (o < 52)  return wk[(o - 48) * HDIM + h] * bql[h];
    else if (o < 56)  return wk[(o - 52) * HDIM + h] * bkl[h];
    else if (o < 60)  return bvl[h] * wo[h * 4 + (o - 56)];
    else if (o == 60) return bql[h] * bkl[h];
    else              return bkl[h] * bkl[h];
}

__global__ void k_consts(const float* __restrict__ Wq, const float* __restrict__ bq,
                         const float* __restrict__ Wk, const float* __restrict__ bk,
                         const float* __restrict__ Wv, const float* __restrict__ bv,
                         const float* __restrict__ Wo, const float* __restrict__ bo,
                         const float* __restrict__ bw,
                         const float* __restrict__ W1, const float* __restrict__ b1,
                         const float* __restrict__ W2)
{
    int l = blockIdx.x;
    int tid = threadIdx.x;          // 0..1023
    int w = tid >> 5, lane = tid & 31;
    __shared__ float acc[64];

    // --- pack FFN weights: one f-pair per thread (tid < FREC) ---
    if (tid < FREC) {
        int f = 2 * tid;
        const float* w1 = W1 + l * 4 * FDIM;
        const float* w2 = W2 + l * FDIM * 4;
        d_f1[l][tid] = make_ulonglong2(pk2(w1[0 * FDIM + f], w1[0 * FDIM + f + 1]),
                                       pk2(w1[1 * FDIM + f], w1[1 * FDIM + f + 1]));
        d_f2[l][tid] = make_ulonglong2(pk2(w1[2 * FDIM + f], w1[2 * FDIM + f + 1]),
                                       pk2(w1[3 * FDIM + f], w1[3 * FDIM + f + 1]));
        d_fb[l][tid] = pk2(b1[l * FDIM + f], b1[l * FDIM + f + 1]);
        float4 r0 = *(const float4*)(w2 + f * 4);
        float4 r1 = *(const float4*)(w2 + (f + 1) * 4);
        d_f3[l][tid] = make_ulonglong2(pk2(r0.x, r1.x), pk2(r0.y, r1.y));
        d_f4[l][tid] = make_ulonglong2(pk2(r0.z, r1.z), pk2(r0.w, r1.w));
    }

    const float* wq  = Wq + l * 4 * HDIM;
    const float* wk  = Wk + l * 4 * HDIM;
    const float* wv  = Wv + l * 4 * HDIM;
    const float* wo  = Wo + l * HDIM * 4;
    const float* bql = bq + l * HDIM;
    const float* bkl = bk + l * HDIM;
    const float* bvl = bv + l * HDIM;

    // warp w computes outputs w and w+32 (if valid)
    #pragma unroll
    for (int pass = 0; pass < 2; ++pass) {
        int o = w + 32 * pass;
        if (o < 62) {
            float s = 0.f;
            #pragma unroll
            for (int c = 0; c < 8; ++c)
                s += prod_for(o, lane + 32 * c, wq, wk, wv, wo, bql, bkl, bvl);
            s += __shfl_xor_sync(0xffffffffu, s, 16);
            s += __shfl_xor_sync(0xffffffffu, s, 8);
            s += __shfl_xor_sync(0xffffffffu, s, 4);
            s += __shfl_xor_sync(0xffffffffu, s, 2);
            s += __shfl_xor_sync(0xffffffffu, s, 1);
            if (lane == 0) acc[o] = s;
        }
    }
    __syncthreads();

    float sc = LOG2E * bw[l] * bw[l];
    LayerConsts* C = &d_consts[l];
    if (tid < 16) {
        C->A2[tid] = sc * acc[tid];
        C->M2[tid] = 0.5f * sc * acc[16 + tid];
        C->Cm[tid] = acc[32 + tid];
    } else if (tid < 20) {
        int i = tid - 16;
        C->cvec[i] = sc * (acc[48 + i] - acc[52 + i]);
        C->d0[i]   = acc[56 + i] + bo[l * 4 + i];
    } else if (tid == 20) {
        C->cconst = sc * (acc[60] - 0.5f * acc[61]);
    }
}

// per-key logit constant c = cconst + sum_i (cvec_i - (M2 x)_i) x_i
__device__ __forceinline__ float cfeat(const LayerConsts& C, float4 xv)
{
    float x[4] = {xv.x, xv.y, xv.z, xv.w};
    float c = C.cconst;
    #pragma unroll
    for (int i = 0; i < 4; ++i) {
        float mi = 0.f;
        #pragma unroll
        for (int j = 0; j < 4; ++j) mi = fmaf(C.M2[i * 4 + j], x[j], mi);
        c = fmaf(C.cvec[i] - mi, x[i], c);
    }
    return c;
}

__device__ __forceinline__ void ln4(float h[4], const float* __restrict__ g,
                                    const float* __restrict__ be, int l)
{
    float mean = 0.25f * (h[0] + h[1] + h[2] + h[3]);
    float e0 = h[0] - mean, e1 = h[1] - mean, e2 = h[2] - mean, e3 = h[3] - mean;
    float var = 0.25f * (e0 * e0 + e1 * e1 + e2 * e2 + e3 * e3);
    float r = rsqrtf(var + 1e-5f);
    h[0] = fmaf(e0 * r, g[l * 4 + 0], be[l * 4 + 0]);
    h[1] = fmaf(e1 * r, g[l * 4 + 1], be[l * 4 + 1]);
    h[2] = fmaf(e2 * r, g[l * 4 + 2], be[l * 4 + 2]);
    h[3] = fmaf(e3 * r, g[l * 4 + 3], be[l * 4 + 3]);
}

// ---------------------------------------------------------------------------
// Fused attention + LN1 + FFN + LN2 (+ next-layer feat / final fc).
// grid (32, 16), 128 threads: thread = (query qid = tid&63, half = tid>>6).
// Each half processes 1024 keys (512 pair-records) and 128 FFN f-pairs;
// halves combine through sRed. f32x2-packed throughout.
// True logit <= 0 (max exactly 0 on diagonal); per-query softmax-invariant
// shift cancels in normalization -> no max pass, no overflow.
// Shared layout (40960 B + 1280 B sRed):
//   [0      , 16384) sKA : per-pair (x0.x,x1.x),(x0.y,x1.y)
//   [16384  , 32768) sKB : per-pair (x0.z,x1.z),(x0.w,x1.w)
//   [32768  , 40960) sKC : per-pair (c0,c1)
// FFN overlay reuses [0, 18432) after the attention loop.
// ---------------------------------------------------------------------------
#define SMEM_BYTES (NREC * 16 + NREC * 16 + NREC * 8)
static_assert(SMEM_BYTES == NREC * 40, "key smem layout mismatch");
static_assert(FREC * 16 * 4 + FREC * 8 <= SMEM_BYTES, "ffn overlay exceeds key smem");
static_assert(SMEM_BYTES + 64 * 5 * 4 <= 48 * 1024, "over static smem limit");

template <int LAYER>
__global__ void __launch_bounds__(128, 5)
k_att(const float* __restrict__ KEY, const float* __restrict__ VAL,
      float* __restrict__ out,
      const float* __restrict__ g1, const float* __restrict__ be1,
      const float* __restrict__ g2, const float* __restrict__ be2,
      const float* __restrict__ b2,
      const float* __restrict__ Wfc, const float* __restrict__ bfc)
{
    __shared__ __align__(16) unsigned char smraw[SMEM_BYTES];
    __shared__ float sRed[64 * 5];
    ulonglong2* sKA = (ulonglong2*)smraw;
    ulonglong2* sKB = (ulonglong2*)(smraw + NREC * 16);
    ull*        sKC = (ull*)(smraw + NREC * 32);
    // FFN overlay (written after attention phase): 18 KB
    ulonglong2* sF1 = (ulonglong2*)smraw;
    ulonglong2* sF2 = sF1 + FREC;
    ulonglong2* sF3 = sF2 + FREC;
    ulonglong2* sF4 = sF3 + FREC;
    ull*        sFB = (ull*)(sF4 + FREC);

    int tid  = threadIdx.x;
    int qid  = tid & 63;
    int half = tid >> 6;
    int base = blockIdx.y * SLEN;
    int q = base + blockIdx.x * 64 + qid;

    const LayerConsts& Cs = d_consts[LAYER];

    // ---- prefill key pairs (all 128 threads) ----
    for (int r = tid; r < NREC; r += 128) {
        int t0 = base + 2 * r;
        float4 x0, x1; float c0, c1;
        if (LAYER == 0) {
            x0 = make_float4(KEY[3 * t0], KEY[3 * t0 + 1], KEY[3 * t0 + 2], VAL[t0]);
            x1 = make_float4(KEY[3 * t0 + 3], KEY[3 * t0 + 4], KEY[3 * t0 + 5], VAL[t0 + 1]);
            c0 = cfeat(Cs, x0);
            c1 = cfeat(Cs, x1);
        } else {
            x0 = d_X[t0]; x1 = d_X[t0 + 1];
            c0 = d_c[t0]; c1 = d_c[t0 + 1];
        }
        sKA[r] = make_ulonglong2(pk2(x0.x, x1.x), pk2(x0.y, x1.y));
        sKB[r] = make_ulonglong2(pk2(x0.z, x1.z), pk2(x0.w, x1.w));
        sKC[r] = pk2(c0, c1);
    }

    float4 xq;
    if (LAYER == 0)
        xq = make_float4(KEY[3 * q], KEY[3 * q + 1], KEY[3 * q + 2], VAL[q]);
    else
        xq = d_X[q];

    // query-folded logit vector gq = A2^T xq, splatted into f32x2 pairs
    float gq0 = xq.x * Cs.A2[0] + xq.y * Cs.A2[4] + xq.z * Cs.A2[8]  + xq.w * Cs.A2[12];
    float gq1 = xq.x * Cs.A2[1] + xq.y * Cs.A2[5] + xq.z * Cs.A2[9]  + xq.w * Cs.A2[13];
    float gq2 = xq.x * Cs.A2[2] + xq.y * Cs.A2[6] + xq.z * Cs.A2[10] + xq.w * Cs.A2[14];
    float gq3 = xq.x * Cs.A2[3] + xq.y * Cs.A2[7] + xq.z * Cs.A2[11] + xq.w * Cs.A2[15];
    ull gx = pk2(gq0, gq0), gy = pk2(gq1, gq1), gz = pk2(gq2, gq2), gw = pk2(gq3, gq3);

    __syncthreads();

    // ---- attention: this half's 512 pair-records ----
    ull sp = 0ull, a0 = 0ull, a1 = 0ull, a2 = 0ull, a3 = 0ull;
    int rbeg = half * (NREC / 2);
    #pragma unroll 4
    for (int r = rbeg; r < rbeg + NREC / 2; ++r) {
        ulonglong2 A = sKA[r];
        ulonglong2 B = sKB[r];
        ull lg = fma2(gx, A.x, sKC[r]);
        lg = fma2(gy, A.y, lg);
        lg = fma2(gz, B.x, lg);
        lg = fma2(gw, B.y, lg);
        float2 lf = upk2(lg);
        ull pp = pk2(fast_exp2(lf.x), fast_exp2(lf.y));
        sp = add2(sp, pp);
        a0 = fma2(pp, A.x, a0);
        a1 = fma2(pp, A.y, a1);
        a2 = fma2(pp, B.x, a2);
        a3 = fma2(pp, B.y, a3);
    }

    // horizontal sums -> 5 scalars
    float2 t2;
    t2 = upk2(sp); float ps  = t2.x + t2.y;
    t2 = upk2(a0); float pa0 = t2.x + t2.y;
    t2 = upk2(a1); float pa1 = t2.x + t2.y;
    t2 = upk2(a2); float pa2 = t2.x + t2.y;
    t2 = upk2(a3); float pa3 = t2.x + t2.y;

    if (half) {
        sRed[qid * 5 + 0] = ps;
        sRed[qid * 5 + 1] = pa0;
        sRed[qid * 5 + 2] = pa1;
        sRed[qid * 5 + 3] = pa2;
        sRed[qid * 5 + 4] = pa3;
    }
    __syncthreads();   // (A) attn loop done everywhere; partials visible

    // key smem dead -> overlay with FFN weights (all threads)
    for (int i = tid; i < FREC; i += 128) {
        sF1[i] = d_f1[LAYER][i];
        sF2[i] = d_f2[LAYER][i];
        sF3[i] = d_f3[LAYER][i];
        sF4[i] = d_f4[LAYER][i];
        sFB[i] = d_fb[LAYER][i];
    }

    float r0, r1, r2, r3;
    if (!half) {
        ps  += sRed[qid * 5 + 0];
        pa0 += sRed[qid * 5 + 1];
        pa1 += sRed[qid * 5 + 2];
        pa2 += sRed[qid * 5 + 3];
        pa3 += sRed[qid * 5 + 4];
        float inv = 1.0f / ps;
        float h[4];
        #pragma unroll
        for (int j = 0; j < 4; ++j) {
            float vj = pa0 * Cs.Cm[0 * 4 + j] + pa1 * Cs.Cm[1 * 4 + j]
                     + pa2 * Cs.Cm[2 * 4 + j] + pa3 * Cs.Cm[3 * 4 + j];
            h[j] = ((&xq.x)[j]) + fmaf(vj, inv, Cs.d0[j]);
        }
        ln4(h, g1, be1, LAYER);
        r0 = h[0]; r1 = h[1]; r2 = h[2]; r3 = h[3];
        sRed[qid * 5 + 0] = r0;
        sRed[qid * 5 + 1] = r1;
        sRed[qid * 5 + 2] = r2;
        sRed[qid * 5 + 3] = r3;
    }
    __syncthreads();   // (B) overlay complete; r broadcast
    if (half) {
        r0 = sRed[qid * 5 + 0];
        r1 = sRed[qid * 5 + 1];
        r2 = sRed[qid * 5 + 2];
        r3 = sRed[qid * 5 + 3];
    }
    ull r0p = pk2(r0, r0), r1p = pk2(r1, r1), r2p = pk2(r2, r2), r3p = pk2(r3, r3);

    // ---- FFN: this half's 128 f-pair records ----
    ull o0 = 0ull, o1 = 0ull, o2 = 0ull, o3 = 0ull;
    int tbeg = half * (FREC / 2);
    #pragma unroll 4
    for (int t = tbeg; t < tbeg + FREC / 2; ++t) {
        ulonglong2 wa = sF1[t], wb = sF2[t];
        ull hp = fma2(r0p, wa.x, sFB[t]);
        hp = fma2(r1p, wa.y, hp);
        hp = fma2(r2p, wb.x, hp);
        hp = fma2(r3p, wb.y, hp);
        float2 hh = upk2(hp);
        ull hr = pk2(fmaxf(hh.x, 0.f), fmaxf(hh.y, 0.f));
        ulonglong2 va = sF3[t], vb = sF4[t];
        o0 = fma2(hr, va.x, o0);
        o1 = fma2(hr, va.y, o1);
        o2 = fma2(hr, vb.x, o2);
        o3 = fma2(hr, vb.y, o3);
    }
    t2 = upk2(o0); float fo0 = t2.x + t2.y;
    t2 = upk2(o1); float fo1 = t2.x + t2.y;
    t2 = upk2(o2); float fo2 = t2.x + t2.y;
    t2 = upk2(o3); float fo3 = t2.x + t2.y;

    if (half) {
        sRed[qid * 5 + 0] = fo0;
        sRed[qid * 5 + 1] = fo1;
        sRed[qid * 5 + 2] = fo2;
        sRed[qid * 5 + 3] = fo3;
    }
    __syncthreads();   // (C) ffn partials visible
    if (!half) {
        fo0 += sRed[qid * 5 + 0];
        fo1 += sRed[qid * 5 + 1];
        fo2 += sRed[qid * 5 + 2];
        fo3 += sRed[qid * 5 + 3];
        float h2[4];
        h2[0] = r0 + fo0 + b2[LAYER * 4 + 0];
        h2[1] = r1 + fo1 + b2[LAYER * 4 + 1];
        h2[2] = r2 + fo2 + b2[LAYER * 4 + 2];
        h2[3] = r3 + fo3 + b2[LAYER * 4 + 3];
        ln4(h2, g2, be2, LAYER);

        if (LAYER == 0) {
            float4 nx = make_float4(h2[0], h2[1], h2[2], h2[3]);
            d_X[q] = nx;
            d_c[q] = cfeat(d_consts[1], nx);
        } else {
            out[q] = fmaf(h2[0], Wfc[0], fmaf(h2[1], Wfc[1],
                     fmaf(h2[2], Wfc[2], fmaf(h2[3], Wfc[3], bfc[0]))));
        }
    }
}

extern "C" void kernel_launch(void* const* d_in, const int* in_sizes, int n_in,
                              void* d_out, int out_size)
{
    const float* KEY   = (const float*)d_in[0];
    const float* VALUE = (const float*)d_in[1];
    const float* Wq    = (const float*)d_in[2];
    const float* bq    = (const float*)d_in[3];
    const float* Wk    = (const float*)d_in[4];
    const float* bk    = (const float*)d_in[5];
    const float* Wv    = (const float*)d_in[6];
    const float* bv    = (const float*)d_in[7];
    const float* Wo    = (const float*)d_in[8];
    const float* bo    = (const float*)d_in[9];
    const float* bw    = (const float*)d_in[10];
    const float* g1    = (const float*)d_in[11];
    const float* be1   = (const float*)d_in[12];
    const float* W1    = (const float*)d_in[13];
    const float* b1    = (const float*)d_in[14];
    const float* W2    = (const float*)d_in[15];
    const float* b2    = (const float*)d_in[16];
    const float* g2    = (const float*)d_in[17];
    const float* be2   = (const float*)d_in[18];
    const float* Wfc   = (const float*)d_in[19];
    const float* bfc   = (const float*)d_in[20];

    k_consts<<<2, 1024>>>(Wq, bq, Wk, bk, Wv, bv, Wo, bo, bw, W1, b1, W2);
    k_att<0><<<dim3(32, 16), 128>>>(KEY, VALUE, nullptr, g1, be1, g2, be2, b2, Wfc, bfc);
    k_att<1><<<dim3(32, 16), 128>>>(KEY, VALUE, (float*)d_out, g1, be1, g2, be2, b2, Wfc, bfc);
}